// round 1
// baseline (speedup 1.0000x reference)
#include <cuda_runtime.h>
#include <cuda_bf16.h>
#include <cstdint>

// ---------------------------------------------------------------------------
// Problem dims (fixed): x[B=32][H=32][W=32][C=512] -> tokens M=32768, Npos=1024/batch
// ---------------------------------------------------------------------------
#define BATCH   32
#define NPOS    1024            // H*W per batch
#define CH      512
#define MTOT    (BATCH * NPOS)  // 32768
#define QKVN    (3 * CH)        // 1536
#define GROUPS  8
#define CPG     (CH / GROUPS)   // 64
#define GN_ELEMS (NPOS * CPG)   // 65536 per (batch, group)

// ---------------------------------------------------------------------------
// Scratch (__device__ globals; allocation-free contract)
// ---------------------------------------------------------------------------
__device__ __align__(256) __nv_bfloat16 g_h[(size_t)MTOT * CH];            // 33.5 MB
__device__ __align__(256) __nv_bfloat16 g_wqkvT[(size_t)QKVN * CH];        // 1.6 MB  [d][c]
__device__ __align__(256) __nv_bfloat16 g_wprojT[(size_t)CH * CH];         // 0.5 MB  [d][c]
__device__ __align__(256) __nv_bfloat16 g_qkv[(size_t)MTOT * QKVN];        // 100 MB  [bn][d]
__device__ __align__(256) __nv_bfloat16 g_vT[(size_t)BATCH * CH * NPOS];   // 33.5 MB [b][c][m]
__device__ __align__(256) float         g_scores[(size_t)BATCH * NPOS * NPOS]; // 134 MB
__device__ __align__(256) __nv_bfloat16 g_probs[(size_t)BATCH * NPOS * NPOS];  // 67 MB
__device__ __align__(256) __nv_bfloat16 g_attn[(size_t)MTOT * CH];         // 33.5 MB

// ---------------------------------------------------------------------------
// GroupNorm: one block per (batch, group). Two passes over x, write bf16 h.
// ---------------------------------------------------------------------------
__global__ __launch_bounds__(256) void groupnorm_kernel(
    const float* __restrict__ x, const float* __restrict__ gamma,
    const float* __restrict__ beta)
{
    const int b = blockIdx.x >> 3;
    const int grp = blockIdx.x & 7;
    const float* base = x + (size_t)b * NPOS * CH + grp * CPG;
    __nv_bfloat16* hout = g_h + (size_t)b * NPOS * CH + grp * CPG;

    float s = 0.f, s2 = 0.f;
    for (int idx = threadIdx.x; idx < GN_ELEMS; idx += 256) {
        int n = idx >> 6, c = idx & 63;
        float v = base[n * CH + c];
        s += v; s2 += v * v;
    }
    __shared__ float red0[8], red1[8];
    #pragma unroll
    for (int o = 16; o; o >>= 1) {
        s  += __shfl_xor_sync(0xffffffffu, s, o);
        s2 += __shfl_xor_sync(0xffffffffu, s2, o);
    }
    if ((threadIdx.x & 31) == 0) { red0[threadIdx.x >> 5] = s; red1[threadIdx.x >> 5] = s2; }
    __syncthreads();
    float ts = 0.f, ts2 = 0.f;
    #pragma unroll
    for (int j = 0; j < 8; j++) { ts += red0[j]; ts2 += red1[j]; }
    const float inv_n = 1.f / (float)GN_ELEMS;
    float mean = ts * inv_n;
    float var  = ts2 * inv_n - mean * mean;
    float rstd = rsqrtf(var + 1e-3f);

    for (int idx = threadIdx.x; idx < GN_ELEMS; idx += 256) {
        int n = idx >> 6, c = idx & 63;
        float v = base[n * CH + c];
        float r = (v - mean) * rstd * gamma[grp * CPG + c] + beta[grp * CPG + c];
        hout[n * CH + c] = __float2bfloat16_rn(r);
    }
}

// ---------------------------------------------------------------------------
// fp32 -> bf16 transpose of weights: in[R][Ccol] -> out[Ccol][R]
// ---------------------------------------------------------------------------
__global__ void transpose_w_kernel(const float* __restrict__ in,
                                   __nv_bfloat16* __restrict__ out,
                                   int R, int Ccol)
{
    __shared__ float tile[32][33];
    int c0 = blockIdx.x * 32, r0 = blockIdx.y * 32;
    int tx = threadIdx.x, ty = threadIdx.y;   // block (32, 8)
    #pragma unroll
    for (int i = 0; i < 32; i += 8)
        tile[ty + i][tx] = in[(size_t)(r0 + ty + i) * Ccol + c0 + tx];
    __syncthreads();
    #pragma unroll
    for (int i = 0; i < 32; i += 8)
        out[(size_t)(c0 + ty + i) * R + r0 + tx] = __float2bfloat16_rn(tile[tx][ty + i]);
}

// ---------------------------------------------------------------------------
// v transpose: qkv[b*NPOS+m][1024+c] -> vT[b][c][m]
// ---------------------------------------------------------------------------
__global__ void transpose_v_kernel()
{
    __shared__ __nv_bfloat16 tile[32][33];
    int b = blockIdx.z;
    const __nv_bfloat16* in = g_qkv + (size_t)b * NPOS * QKVN + 2 * CH;
    __nv_bfloat16* out = g_vT + (size_t)b * CH * NPOS;
    int m0 = blockIdx.x * 32, c0 = blockIdx.y * 32;
    int tx = threadIdx.x, ty = threadIdx.y;   // block (32, 8)
    #pragma unroll
    for (int i = 0; i < 32; i += 8)
        tile[ty + i][tx] = in[(size_t)(m0 + ty + i) * QKVN + c0 + tx];
    __syncthreads();
    #pragma unroll
    for (int i = 0; i < 32; i += 8)
        out[(size_t)(c0 + ty + i) * NPOS + m0 + tx] = tile[tx][ty + i];
}

// ---------------------------------------------------------------------------
// Softmax over rows of 1024: fp32 scores -> bf16 probs. One block per row.
// ---------------------------------------------------------------------------
__global__ __launch_bounds__(256) void softmax_kernel()
{
    const size_t row = blockIdx.x;
    const float* s = g_scores + row * NPOS;
    __nv_bfloat16* p = g_probs + row * NPOS;
    const int tid = threadIdx.x;
    __shared__ float red[8];

    float v[4];
    float mx = -1e30f;
    #pragma unroll
    for (int i = 0; i < 4; i++) { v[i] = s[tid + 256 * i]; mx = fmaxf(mx, v[i]); }
    #pragma unroll
    for (int o = 16; o; o >>= 1) mx = fmaxf(mx, __shfl_xor_sync(0xffffffffu, mx, o));
    if ((tid & 31) == 0) red[tid >> 5] = mx;
    __syncthreads();
    mx = red[0];
    #pragma unroll
    for (int j = 1; j < 8; j++) mx = fmaxf(mx, red[j]);

    float sum = 0.f;
    #pragma unroll
    for (int i = 0; i < 4; i++) { v[i] = __expf(v[i] - mx); sum += v[i]; }
    __syncthreads();
    #pragma unroll
    for (int o = 16; o; o >>= 1) sum += __shfl_xor_sync(0xffffffffu, sum, o);
    if ((tid & 31) == 0) red[tid >> 5] = sum;
    __syncthreads();
    float tot = 0.f;
    #pragma unroll
    for (int j = 0; j < 8; j++) tot += red[j];
    float rinv = 1.f / tot;
    #pragma unroll
    for (int i = 0; i < 4; i++) p[tid + 256 * i] = __float2bfloat16_rn(v[i] * rinv);
}

// ---------------------------------------------------------------------------
// Generic NT bf16 GEMM: C[M][N] = A[M][K] * B[N][K]^T  (both K-contiguous)
// mma.sync.m16n8k16 bf16 -> fp32. BM=128, BN=128, BK=32, 8 warps (4x2).
// EPI: 0 = bf16 + bias   (QKV)
//      1 = fp32 * scale  (scores)
//      2 = bf16 plain    (attn out)
//      3 = fp32 + bias + residual (proj)
// ---------------------------------------------------------------------------
#define BM 128
#define BN 128
#define BK 32
#define KPAD 8

template <int EPI>
__global__ __launch_bounds__(256, 1) void gemm_nt(
    const __nv_bfloat16* __restrict__ A, int lda, long long sA,
    const __nv_bfloat16* __restrict__ B, int ldb, long long sB,
    void* __restrict__ Cv, int ldc, long long sC,
    const float* __restrict__ bias, const float* __restrict__ resid,
    float scale, int K)
{
    __shared__ __align__(16) __nv_bfloat16 As[BM][BK + KPAD];
    __shared__ __align__(16) __nv_bfloat16 Bs[BN][BK + KPAD];

    const int z = blockIdx.z;
    A += (size_t)z * sA;
    B += (size_t)z * sB;

    const int tid = threadIdx.x;
    const int wid = tid >> 5, lane = tid & 31;
    const int wm = wid & 3, wn = wid >> 2;   // warp tile: 32 rows x 64 cols
    const int g = lane >> 2, t = lane & 3;
    const int m0 = blockIdx.y * BM;
    const int n0 = blockIdx.x * BN;

    float acc[2][8][4];
    #pragma unroll
    for (int i = 0; i < 2; i++)
        #pragma unroll
        for (int j = 0; j < 8; j++)
            #pragma unroll
            for (int c = 0; c < 4; c++) acc[i][j][c] = 0.f;

    for (int k0 = 0; k0 < K; k0 += BK) {
        #pragma unroll
        for (int i = 0; i < 2; i++) {
            int id = tid + i * 256;
            int r = id >> 2;
            int cc = (id & 3) * 8;
            *(uint4*)&As[r][cc] = *(const uint4*)&A[(size_t)(m0 + r) * lda + k0 + cc];
            *(uint4*)&Bs[r][cc] = *(const uint4*)&B[(size_t)(n0 + r) * ldb + k0 + cc];
        }
        __syncthreads();
        #pragma unroll
        for (int kk = 0; kk < BK; kk += 16) {
            uint32_t af[2][4], bf[8][2];
            #pragma unroll
            for (int mi = 0; mi < 2; mi++) {
                int r = wm * 32 + mi * 16;
                af[mi][0] = *(const uint32_t*)&As[r + g    ][kk + t * 2];
                af[mi][1] = *(const uint32_t*)&As[r + g + 8][kk + t * 2];
                af[mi][2] = *(const uint32_t*)&As[r + g    ][kk + t * 2 + 8];
                af[mi][3] = *(const uint32_t*)&As[r + g + 8][kk + t * 2 + 8];
            }
            #pragma unroll
            for (int ni = 0; ni < 8; ni++) {
                int r = wn * 64 + ni * 8 + g;
                bf[ni][0] = *(const uint32_t*)&Bs[r][kk + t * 2];
                bf[ni][1] = *(const uint32_t*)&Bs[r][kk + t * 2 + 8];
            }
            #pragma unroll
            for (int mi = 0; mi < 2; mi++)
                #pragma unroll
                for (int ni = 0; ni < 8; ni++) {
                    asm volatile(
                        "mma.sync.aligned.m16n8k16.row.col.f32.bf16.bf16.f32 "
                        "{%0,%1,%2,%3}, {%4,%5,%6,%7}, {%8,%9}, {%0,%1,%2,%3};\n"
                        : "+f"(acc[mi][ni][0]), "+f"(acc[mi][ni][1]),
                          "+f"(acc[mi][ni][2]), "+f"(acc[mi][ni][3])
                        : "r"(af[mi][0]), "r"(af[mi][1]), "r"(af[mi][2]), "r"(af[mi][3]),
                          "r"(bf[ni][0]), "r"(bf[ni][1]));
                }
        }
        __syncthreads();
    }

    const size_t cbase = (size_t)z * sC;
    #pragma unroll
    for (int mi = 0; mi < 2; mi++) {
        #pragma unroll
        for (int ni = 0; ni < 8; ni++) {
            int row0 = m0 + wm * 32 + mi * 16 + g;
            int col  = n0 + wn * 64 + ni * 8 + t * 2;
            #pragma unroll
            for (int h2 = 0; h2 < 2; h2++) {
                int row = row0 + h2 * 8;
                float v0 = acc[mi][ni][h2 * 2 + 0];
                float v1 = acc[mi][ni][h2 * 2 + 1];
                size_t off = cbase + (size_t)row * ldc + col;
                if (EPI == 0) {
                    __nv_bfloat162 pk = __floats2bfloat162_rn(v0 + bias[col], v1 + bias[col + 1]);
                    *(__nv_bfloat162*)((__nv_bfloat16*)Cv + off) = pk;
                } else if (EPI == 1) {
                    float2 pk = make_float2(v0 * scale, v1 * scale);
                    *(float2*)((float*)Cv + off) = pk;
                } else if (EPI == 2) {
                    *(__nv_bfloat162*)((__nv_bfloat16*)Cv + off) = __floats2bfloat162_rn(v0, v1);
                } else {
                    float2 rx = *(const float2*)&resid[off];
                    float2 pk = make_float2(v0 + bias[col] + rx.x, v1 + bias[col + 1] + rx.y);
                    *(float2*)((float*)Cv + off) = pk;
                }
            }
        }
    }
}

// ---------------------------------------------------------------------------
// Launch
// ---------------------------------------------------------------------------
extern "C" void kernel_launch(void* const* d_in, const int* in_sizes, int n_in,
                              void* d_out, int out_size)
{
    const float* x      = (const float*)d_in[0];
    const float* gamma  = (const float*)d_in[1];
    const float* beta   = (const float*)d_in[2];
    const float* w_qkv  = (const float*)d_in[3];
    const float* b_qkv  = (const float*)d_in[4];
    const float* w_proj = (const float*)d_in[5];
    const float* b_proj = (const float*)d_in[6];
    float* out = (float*)d_out;

    void *p_h, *p_wqkvT, *p_wprojT, *p_qkv, *p_vT, *p_scores, *p_probs, *p_attn;
    cudaGetSymbolAddress(&p_h, g_h);
    cudaGetSymbolAddress(&p_wqkvT, g_wqkvT);
    cudaGetSymbolAddress(&p_wprojT, g_wprojT);
    cudaGetSymbolAddress(&p_qkv, g_qkv);
    cudaGetSymbolAddress(&p_vT, g_vT);
    cudaGetSymbolAddress(&p_scores, g_scores);
    cudaGetSymbolAddress(&p_probs, g_probs);
    cudaGetSymbolAddress(&p_attn, g_attn);

    const __nv_bfloat16* hB      = (const __nv_bfloat16*)p_h;
    const __nv_bfloat16* wqkvTB  = (const __nv_bfloat16*)p_wqkvT;
    const __nv_bfloat16* wprojTB = (const __nv_bfloat16*)p_wprojT;
    const __nv_bfloat16* qkvB    = (const __nv_bfloat16*)p_qkv;
    const __nv_bfloat16* vTB     = (const __nv_bfloat16*)p_vT;
    const __nv_bfloat16* probsB  = (const __nv_bfloat16*)p_probs;
    const __nv_bfloat16* attnB   = (const __nv_bfloat16*)p_attn;

    // 1) weight transposes (fp32 -> bf16, [N][K])
    transpose_w_kernel<<<dim3(QKVN / 32, CH / 32), dim3(32, 8)>>>(w_qkv, (__nv_bfloat16*)p_wqkvT, CH, QKVN);
    transpose_w_kernel<<<dim3(CH / 32, CH / 32), dim3(32, 8)>>>(w_proj, (__nv_bfloat16*)p_wprojT, CH, CH);

    // 2) GroupNorm -> h (bf16)
    groupnorm_kernel<<<BATCH * GROUPS, 256>>>(x, gamma, beta);

    // 3) QKV GEMM: [32768,512] x [1536,512]^T -> qkv bf16 (+bias)
    gemm_nt<0><<<dim3(QKVN / BN, MTOT / BM, 1), 256>>>(
        hB, CH, 0, wqkvTB, CH, 0, p_qkv, QKVN, 0, b_qkv, nullptr, 0.f, CH);

    // 4) v -> vT
    transpose_v_kernel<<<dim3(NPOS / 32, CH / 32, BATCH), dim3(32, 8)>>>();

    // 5) scores: per batch, q x k^T * scale -> fp32
    const float scale = 0.044194173824159216f; // 1/sqrt(512)
    gemm_nt<1><<<dim3(NPOS / BN, NPOS / BM, BATCH), 256>>>(
        qkvB, QKVN, (long long)NPOS * QKVN,
        qkvB + CH, QKVN, (long long)NPOS * QKVN,
        p_scores, NPOS, (long long)NPOS * NPOS,
        nullptr, nullptr, scale, CH);

    // 6) softmax rows -> bf16 probs
    softmax_kernel<<<MTOT, 256>>>();

    // 7) attn = P x vT^T : [1024,1024] x [512,1024]^T -> bf16
    gemm_nt<2><<<dim3(CH / BN, NPOS / BM, BATCH), 256>>>(
        probsB, NPOS, (long long)NPOS * NPOS,
        vTB, NPOS, (long long)CH * NPOS,
        p_attn, CH, (long long)NPOS * CH,
        nullptr, nullptr, 0.f, NPOS);

    // 8) proj + bias + residual -> out fp32
    gemm_nt<3><<<dim3(CH / BN, MTOT / BM, 1), 256>>>(
        attnB, CH, 0, wprojTB, CH, 0, d_out, CH, 0, b_proj, x, 0.f, CH);
}

// round 2
// speedup vs baseline: 1.7921x; 1.7921x over previous
#include <cuda_runtime.h>
#include <cuda_bf16.h>
#include <cstdint>

// ---------------------------------------------------------------------------
// Problem dims (fixed)
// ---------------------------------------------------------------------------
#define BATCH   32
#define NPOS    1024
#define CH      512
#define MTOT    (BATCH * NPOS)
#define QKVN    (3 * CH)
#define GROUPS  8
#define CPG     (CH / GROUPS)
#define GN_ELEMS (NPOS * CPG)

// GEMM tiling
#define BM 128
#define BN 128
#define BK 32
#define KPAD 8
#define RS (BK + KPAD)            // 40 elems/row -> 80B, 20-bank skew (conflict-free)
#define STAGES 4
#define STG_ELEMS (BM * RS)       // per-stage per-matrix elems
#define SMEM_BYTES (STAGES * 2 * STG_ELEMS * 2)   // 81920 B

// ---------------------------------------------------------------------------
// Scratch
// ---------------------------------------------------------------------------
__device__ __align__(256) __nv_bfloat16 g_h[(size_t)MTOT * CH];
__device__ __align__(256) __nv_bfloat16 g_wqkvT[(size_t)QKVN * CH];
__device__ __align__(256) __nv_bfloat16 g_wprojT[(size_t)CH * CH];
__device__ __align__(256) __nv_bfloat16 g_qkv[(size_t)MTOT * QKVN];
__device__ __align__(256) __nv_bfloat16 g_vT[(size_t)BATCH * CH * NPOS];
__device__ __align__(256) float         g_scores[(size_t)BATCH * NPOS * NPOS];
__device__ __align__(256) __nv_bfloat16 g_probs[(size_t)BATCH * NPOS * NPOS];
__device__ __align__(256) __nv_bfloat16 g_attn[(size_t)MTOT * CH];

// ---------------------------------------------------------------------------
// Helpers
// ---------------------------------------------------------------------------
__device__ __forceinline__ void cp16(uint32_t dst, const void* src) {
    asm volatile("cp.async.cg.shared.global [%0], [%1], 16;\n" :: "r"(dst), "l"(src));
}
__device__ __forceinline__ void ldm4(uint32_t& r0, uint32_t& r1, uint32_t& r2, uint32_t& r3,
                                     uint32_t addr) {
    asm volatile("ldmatrix.sync.aligned.m8n8.x4.shared.b16 {%0,%1,%2,%3}, [%4];\n"
                 : "=r"(r0), "=r"(r1), "=r"(r2), "=r"(r3) : "r"(addr));
}

// ---------------------------------------------------------------------------
// GroupNorm (vectorized)
// ---------------------------------------------------------------------------
__global__ __launch_bounds__(256) void groupnorm_kernel(
    const float* __restrict__ x, const float* __restrict__ gamma,
    const float* __restrict__ beta)
{
    const int b = blockIdx.x >> 3;
    const int grp = blockIdx.x & 7;
    const float* base = x + (size_t)b * NPOS * CH + grp * CPG;
    __nv_bfloat16* hout = g_h + (size_t)b * NPOS * CH + grp * CPG;
    const float4* base4 = (const float4*)base;

    float s = 0.f, s2 = 0.f;
    for (int idx = threadIdx.x; idx < GN_ELEMS / 4; idx += 256) {
        int n = idx >> 4, c4 = idx & 15;
        float4 v = base4[n * (CH / 4) + c4];
        s  += v.x + v.y + v.z + v.w;
        s2 += v.x * v.x + v.y * v.y + v.z * v.z + v.w * v.w;
    }
    __shared__ float red0[8], red1[8];
    #pragma unroll
    for (int o = 16; o; o >>= 1) {
        s  += __shfl_xor_sync(0xffffffffu, s, o);
        s2 += __shfl_xor_sync(0xffffffffu, s2, o);
    }
    if ((threadIdx.x & 31) == 0) { red0[threadIdx.x >> 5] = s; red1[threadIdx.x >> 5] = s2; }
    __syncthreads();
    float ts = 0.f, ts2 = 0.f;
    #pragma unroll
    for (int j = 0; j < 8; j++) { ts += red0[j]; ts2 += red1[j]; }
    const float inv_n = 1.f / (float)GN_ELEMS;
    float mean = ts * inv_n;
    float rstd = rsqrtf(ts2 * inv_n - mean * mean + 1e-3f);

    for (int idx = threadIdx.x; idx < GN_ELEMS / 4; idx += 256) {
        int n = idx >> 4, c4 = idx & 15;
        float4 v = base4[n * (CH / 4) + c4];
        int c = c4 * 4;
        float r0 = (v.x - mean) * rstd * gamma[grp * CPG + c]     + beta[grp * CPG + c];
        float r1 = (v.y - mean) * rstd * gamma[grp * CPG + c + 1] + beta[grp * CPG + c + 1];
        float r2 = (v.z - mean) * rstd * gamma[grp * CPG + c + 2] + beta[grp * CPG + c + 2];
        float r3 = (v.w - mean) * rstd * gamma[grp * CPG + c + 3] + beta[grp * CPG + c + 3];
        union { uint2 u; __nv_bfloat162 h2[2]; } pk;
        pk.h2[0] = __floats2bfloat162_rn(r0, r1);
        pk.h2[1] = __floats2bfloat162_rn(r2, r3);
        *(uint2*)&hout[n * CH + c] = pk.u;
    }
}

// ---------------------------------------------------------------------------
// Weight transpose (fp32 -> bf16, [N][K])
// ---------------------------------------------------------------------------
__global__ void transpose_w_kernel(const float* __restrict__ in,
                                   __nv_bfloat16* __restrict__ out,
                                   int R, int Ccol)
{
    __shared__ float tile[32][33];
    int c0 = blockIdx.x * 32, r0 = blockIdx.y * 32;
    int tx = threadIdx.x, ty = threadIdx.y;
    #pragma unroll
    for (int i = 0; i < 32; i += 8)
        tile[ty + i][tx] = in[(size_t)(r0 + ty + i) * Ccol + c0 + tx];
    __syncthreads();
    #pragma unroll
    for (int i = 0; i < 32; i += 8)
        out[(size_t)(c0 + ty + i) * R + r0 + tx] = __float2bfloat16_rn(tile[tx][ty + i]);
}

__global__ void transpose_v_kernel()
{
    __shared__ __nv_bfloat16 tile[32][33];
    int b = blockIdx.z;
    const __nv_bfloat16* in = g_qkv + (size_t)b * NPOS * QKVN + 2 * CH;
    __nv_bfloat16* out = g_vT + (size_t)b * CH * NPOS;
    int m0 = blockIdx.x * 32, c0 = blockIdx.y * 32;
    int tx = threadIdx.x, ty = threadIdx.y;
    #pragma unroll
    for (int i = 0; i < 32; i += 8)
        tile[ty + i][tx] = in[(size_t)(m0 + ty + i) * QKVN + c0 + tx];
    __syncthreads();
    #pragma unroll
    for (int i = 0; i < 32; i += 8)
        out[(size_t)(c0 + ty + i) * NPOS + m0 + tx] = tile[tx][ty + i];
}

// ---------------------------------------------------------------------------
// Softmax (vectorized): fp32 scores -> bf16 probs
// ---------------------------------------------------------------------------
__global__ __launch_bounds__(256) void softmax_kernel()
{
    const size_t row = blockIdx.x;
    const float4* s4 = (const float4*)(g_scores + row * NPOS);
    __nv_bfloat16* p = g_probs + row * NPOS;
    const int tid = threadIdx.x;
    __shared__ float red[8];

    float4 v = s4[tid];
    float mx = fmaxf(fmaxf(v.x, v.y), fmaxf(v.z, v.w));
    #pragma unroll
    for (int o = 16; o; o >>= 1) mx = fmaxf(mx, __shfl_xor_sync(0xffffffffu, mx, o));
    if ((tid & 31) == 0) red[tid >> 5] = mx;
    __syncthreads();
    mx = red[0];
    #pragma unroll
    for (int j = 1; j < 8; j++) mx = fmaxf(mx, red[j]);

    v.x = __expf(v.x - mx); v.y = __expf(v.y - mx);
    v.z = __expf(v.z - mx); v.w = __expf(v.w - mx);
    float sum = v.x + v.y + v.z + v.w;
    __syncthreads();
    #pragma unroll
    for (int o = 16; o; o >>= 1) sum += __shfl_xor_sync(0xffffffffu, sum, o);
    if ((tid & 31) == 0) red[tid >> 5] = sum;
    __syncthreads();
    float tot = 0.f;
    #pragma unroll
    for (int j = 0; j < 8; j++) tot += red[j];
    float rinv = 1.f / tot;
    union { uint2 u; __nv_bfloat162 h2[2]; } pk;
    pk.h2[0] = __floats2bfloat162_rn(v.x * rinv, v.y * rinv);
    pk.h2[1] = __floats2bfloat162_rn(v.z * rinv, v.w * rinv);
    *(uint2*)&p[tid * 4] = pk.u;
}

// ---------------------------------------------------------------------------
// NT bf16 GEMM, 4-stage cp.async pipeline + ldmatrix.
// C[M][N] = A[M][K] * B[N][K]^T. BM=BN=128, BK=32, 8 warps (4x2).
// ---------------------------------------------------------------------------
template <int EPI>
__global__ __launch_bounds__(256, 1) void gemm_nt(
    const __nv_bfloat16* __restrict__ A, int lda, long long sA,
    const __nv_bfloat16* __restrict__ B, int ldb, long long sB,
    void* __restrict__ Cv, int ldc, long long sC,
    const float* __restrict__ bias, const float* __restrict__ resid,
    float scale, int K)
{
    extern __shared__ __nv_bfloat16 sm[];
    __nv_bfloat16* Asm = sm;
    __nv_bfloat16* Bsm = sm + STAGES * STG_ELEMS;

    const int z = blockIdx.z;
    A += (size_t)z * sA;
    B += (size_t)z * sB;

    const int tid = threadIdx.x;
    const int wid = tid >> 5, lane = tid & 31;
    const int wm = wid & 3, wn = wid >> 2;
    const int g = lane >> 2, t = lane & 3;
    const int m0 = blockIdx.y * BM;
    const int n0 = blockIdx.x * BN;

    const uint32_t sa_base = (uint32_t)__cvta_generic_to_shared(Asm);
    const uint32_t sb_base = (uint32_t)__cvta_generic_to_shared(Bsm);

    // cp.async thread mapping: 2 rows (r, r+64) x 1 16B chunk per matrix
    const int r_ld = tid >> 2;
    const int c_ld = (tid & 3) * 8;

    // ldmatrix lane mapping
    const int laneRow  = lane & 15;
    const int laneColH = (lane >> 4) * 8;
    const uint32_t aAddr0 = sa_base + (((wm * 32 + laneRow) * RS + laneColH) << 1);
    const uint32_t bAddr0 = sb_base + (((wn * 64 + laneRow) * RS + laneColH) << 1);

    float acc[2][8][4] = {};

    const int kit = K / BK;

#define LOAD_STAGE(s, ki) do {                                                     \
        int _k0 = (ki) * BK;                                                       \
        uint32_t _da = sa_base + (s) * (STG_ELEMS * 2);                            \
        uint32_t _db = sb_base + (s) * (STG_ELEMS * 2);                            \
        cp16(_da + (r_ld * RS + c_ld) * 2,        A + (size_t)(m0 + r_ld) * lda + _k0 + c_ld);        \
        cp16(_da + ((r_ld + 64) * RS + c_ld) * 2, A + (size_t)(m0 + r_ld + 64) * lda + _k0 + c_ld);   \
        cp16(_db + (r_ld * RS + c_ld) * 2,        B + (size_t)(n0 + r_ld) * ldb + _k0 + c_ld);        \
        cp16(_db + ((r_ld + 64) * RS + c_ld) * 2, B + (size_t)(n0 + r_ld + 64) * ldb + _k0 + c_ld);   \
        asm volatile("cp.async.commit_group;\n");                                  \
    } while (0)

    LOAD_STAGE(0, 0);
    LOAD_STAGE(1, 1);
    LOAD_STAGE(2, 2);

    for (int ki = 0; ki < kit; ki++) {
        asm volatile("cp.async.wait_group 2;\n");
        __syncthreads();
        const int st = ki & (STAGES - 1);
        const uint32_t aoff = aAddr0 + st * (STG_ELEMS * 2);
        const uint32_t boff = bAddr0 + st * (STG_ELEMS * 2);

        #pragma unroll
        for (int kk = 0; kk < BK; kk += 16) {
            uint32_t af[2][4], bf[8][2];
            ldm4(af[0][0], af[0][1], af[0][2], af[0][3], aoff + kk * 2);
            ldm4(af[1][0], af[1][1], af[1][2], af[1][3], aoff + (16 * RS + kk) * 2);
            #pragma unroll
            for (int p = 0; p < 4; p++) {
                uint32_t q0, q1, q2, q3;
                ldm4(q0, q1, q2, q3, boff + (p * 16 * RS + kk) * 2);
                bf[2 * p][0] = q0; bf[2 * p + 1][0] = q1;
                bf[2 * p][1] = q2; bf[2 * p + 1][1] = q3;
            }
            #pragma unroll
            for (int mi = 0; mi < 2; mi++)
                #pragma unroll
                for (int ni = 0; ni < 8; ni++) {
                    asm volatile(
                        "mma.sync.aligned.m16n8k16.row.col.f32.bf16.bf16.f32 "
                        "{%0,%1,%2,%3}, {%4,%5,%6,%7}, {%8,%9}, {%0,%1,%2,%3};\n"
                        : "+f"(acc[mi][ni][0]), "+f"(acc[mi][ni][1]),
                          "+f"(acc[mi][ni][2]), "+f"(acc[mi][ni][3])
                        : "r"(af[mi][0]), "r"(af[mi][1]), "r"(af[mi][2]), "r"(af[mi][3]),
                          "r"(bf[ni][0]), "r"(bf[ni][1]));
                }
        }

        if (ki + STAGES - 1 < kit) {
            LOAD_STAGE((ki + STAGES - 1) & (STAGES - 1), ki + STAGES - 1);
        } else {
            asm volatile("cp.async.commit_group;\n");
        }
    }
#undef LOAD_STAGE

    const size_t cbase = (size_t)z * sC;
    #pragma unroll
    for (int mi = 0; mi < 2; mi++) {
        #pragma unroll
        for (int ni = 0; ni < 8; ni++) {
            int row0 = m0 + wm * 32 + mi * 16 + g;
            int col  = n0 + wn * 64 + ni * 8 + t * 2;
            #pragma unroll
            for (int h2 = 0; h2 < 2; h2++) {
                int row = row0 + h2 * 8;
                float v0 = acc[mi][ni][h2 * 2 + 0];
                float v1 = acc[mi][ni][h2 * 2 + 1];
                size_t off = cbase + (size_t)row * ldc + col;
                if (EPI == 0) {
                    __nv_bfloat162 pk = __floats2bfloat162_rn(v0 + bias[col], v1 + bias[col + 1]);
                    *(__nv_bfloat162*)((__nv_bfloat16*)Cv + off) = pk;
                } else if (EPI == 1) {
                    *(float2*)((float*)Cv + off) = make_float2(v0 * scale, v1 * scale);
                } else if (EPI == 2) {
                    *(__nv_bfloat162*)((__nv_bfloat16*)Cv + off) = __floats2bfloat162_rn(v0, v1);
                } else {
                    float2 rx = *(const float2*)&resid[off];
                    *(float2*)((float*)Cv + off) =
                        make_float2(v0 + bias[col] + rx.x, v1 + bias[col + 1] + rx.y);
                }
            }
        }
    }
}

// ---------------------------------------------------------------------------
// Launch
// ---------------------------------------------------------------------------
extern "C" void kernel_launch(void* const* d_in, const int* in_sizes, int n_in,
                              void* d_out, int out_size)
{
    const float* x      = (const float*)d_in[0];
    const float* gamma  = (const float*)d_in[1];
    const float* beta   = (const float*)d_in[2];
    const float* w_qkv  = (const float*)d_in[3];
    const float* b_qkv  = (const float*)d_in[4];
    const float* w_proj = (const float*)d_in[5];
    const float* b_proj = (const float*)d_in[6];

    cudaFuncSetAttribute(gemm_nt<0>, cudaFuncAttributeMaxDynamicSharedMemorySize, SMEM_BYTES);
    cudaFuncSetAttribute(gemm_nt<1>, cudaFuncAttributeMaxDynamicSharedMemorySize, SMEM_BYTES);
    cudaFuncSetAttribute(gemm_nt<2>, cudaFuncAttributeMaxDynamicSharedMemorySize, SMEM_BYTES);
    cudaFuncSetAttribute(gemm_nt<3>, cudaFuncAttributeMaxDynamicSharedMemorySize, SMEM_BYTES);

    void *p_h, *p_wqkvT, *p_wprojT, *p_qkv, *p_vT, *p_scores, *p_probs, *p_attn;
    cudaGetSymbolAddress(&p_h, g_h);
    cudaGetSymbolAddress(&p_wqkvT, g_wqkvT);
    cudaGetSymbolAddress(&p_wprojT, g_wprojT);
    cudaGetSymbolAddress(&p_qkv, g_qkv);
    cudaGetSymbolAddress(&p_vT, g_vT);
    cudaGetSymbolAddress(&p_scores, g_scores);
    cudaGetSymbolAddress(&p_probs, g_probs);
    cudaGetSymbolAddress(&p_attn, g_attn);

    const __nv_bfloat16* hB      = (const __nv_bfloat16*)p_h;
    const __nv_bfloat16* wqkvTB  = (const __nv_bfloat16*)p_wqkvT;
    const __nv_bfloat16* wprojTB = (const __nv_bfloat16*)p_wprojT;
    const __nv_bfloat16* qkvB    = (const __nv_bfloat16*)p_qkv;
    const __nv_bfloat16* vTB     = (const __nv_bfloat16*)p_vT;
    const __nv_bfloat16* probsB  = (const __nv_bfloat16*)p_probs;
    const __nv_bfloat16* attnB   = (const __nv_bfloat16*)p_attn;

    transpose_w_kernel<<<dim3(QKVN / 32, CH / 32), dim3(32, 8)>>>(w_qkv, (__nv_bfloat16*)p_wqkvT, CH, QKVN);
    transpose_w_kernel<<<dim3(CH / 32, CH / 32), dim3(32, 8)>>>(w_proj, (__nv_bfloat16*)p_wprojT, CH, CH);
    groupnorm_kernel<<<BATCH * GROUPS, 256>>>(x, gamma, beta);

    gemm_nt<0><<<dim3(QKVN / BN, MTOT / BM, 1), 256, SMEM_BYTES>>>(
        hB, CH, 0, wqkvTB, CH, 0, p_qkv, QKVN, 0, b_qkv, nullptr, 0.f, CH);

    transpose_v_kernel<<<dim3(NPOS / 32, CH / 32, BATCH), dim3(32, 8)>>>();

    const float scale = 0.044194173824159216f; // 1/sqrt(512)
    gemm_nt<1><<<dim3(NPOS / BN, NPOS / BM, BATCH), 256, SMEM_BYTES>>>(
        qkvB, QKVN, (long long)NPOS * QKVN,
        qkvB + CH, QKVN, (long long)NPOS * QKVN,
        p_scores, NPOS, (long long)NPOS * NPOS,
        nullptr, nullptr, scale, CH);

    softmax_kernel<<<MTOT, 256>>>();

    gemm_nt<2><<<dim3(CH / BN, NPOS / BM, BATCH), 256, SMEM_BYTES>>>(
        probsB, NPOS, (long long)NPOS * NPOS,
        vTB, NPOS, (long long)CH * NPOS,
        p_attn, CH, (long long)NPOS * CH,
        nullptr, nullptr, 0.f, NPOS);

    gemm_nt<3><<<dim3(CH / BN, MTOT / BM, 1), 256, SMEM_BYTES>>>(
        attnB, CH, 0, wprojTB, CH, 0, d_out, CH, 0, b_proj, x, 0.f, CH);
}

// round 4
// speedup vs baseline: 1.8591x; 1.0374x over previous
#include <cuda_runtime.h>
#include <cuda_bf16.h>
#include <cstdint>

// ---------------------------------------------------------------------------
// Problem dims (fixed)
// ---------------------------------------------------------------------------
#define BATCH   32
#define NPOS    1024
#define CH      512
#define MTOT    (BATCH * NPOS)
#define QKVN    (3 * CH)
#define GROUPS  8
#define CPG     (CH / GROUPS)
#define GN_ELEMS (NPOS * CPG)

// GEMM tiling
#define BM 128
#define BN 128
#define BK 32
#define KPAD 8
#define RS (BK + KPAD)            // 40 elems/row -> 80B, 20-bank skew (conflict-free)
#define STAGES 4
#define STG_ELEMS (BM * RS)       // per-stage per-matrix elems
#define SMEM_BYTES (STAGES * 2 * STG_ELEMS * 2)   // 81920 B

// ---------------------------------------------------------------------------
// Scratch
// ---------------------------------------------------------------------------
__device__ __align__(256) __nv_bfloat16 g_h[(size_t)MTOT * CH];
__device__ __align__(256) __nv_bfloat16 g_wqkvT[(size_t)QKVN * CH];
__device__ __align__(256) __nv_bfloat16 g_wprojT[(size_t)CH * CH];
__device__ __align__(256) __nv_bfloat16 g_qkv[(size_t)MTOT * QKVN];
__device__ __align__(256) __nv_bfloat16 g_vT[(size_t)BATCH * CH * NPOS];
__device__ __align__(256) float         g_scores[(size_t)BATCH * NPOS * NPOS];
__device__ __align__(256) __nv_bfloat16 g_probs[(size_t)BATCH * NPOS * NPOS];
__device__ __align__(256) __nv_bfloat16 g_attn[(size_t)MTOT * CH];

// ---------------------------------------------------------------------------
// Helpers
// ---------------------------------------------------------------------------
__device__ __forceinline__ void cp16(uint32_t dst, const void* src) {
    asm volatile("cp.async.cg.shared.global [%0], [%1], 16;\n" :: "r"(dst), "l"(src));
}
__device__ __forceinline__ void ldm4(uint32_t& r0, uint32_t& r1, uint32_t& r2, uint32_t& r3,
                                     uint32_t addr) {
    asm volatile("ldmatrix.sync.aligned.m8n8.x4.shared.b16 {%0,%1,%2,%3}, [%4];\n"
                 : "=r"(r0), "=r"(r1), "=r"(r2), "=r"(r3) : "r"(addr));
}

// ---------------------------------------------------------------------------
// GroupNorm (vectorized)
// ---------------------------------------------------------------------------
__global__ __launch_bounds__(256) void groupnorm_kernel(
    const float* __restrict__ x, const float* __restrict__ gamma,
    const float* __restrict__ beta)
{
    const int b = blockIdx.x >> 3;
    const int grp = blockIdx.x & 7;
    const float* base = x + (size_t)b * NPOS * CH + grp * CPG;
    __nv_bfloat16* hout = g_h + (size_t)b * NPOS * CH + grp * CPG;
    const float4* base4 = (const float4*)base;

    float s = 0.f, s2 = 0.f;
    for (int idx = threadIdx.x; idx < GN_ELEMS / 4; idx += 256) {
        int n = idx >> 4, c4 = idx & 15;
        float4 v = base4[n * (CH / 4) + c4];
        s  += v.x + v.y + v.z + v.w;
        s2 += v.x * v.x + v.y * v.y + v.z * v.z + v.w * v.w;
    }
    __shared__ float red0[8], red1[8];
    #pragma unroll
    for (int o = 16; o; o >>= 1) {
        s  += __shfl_xor_sync(0xffffffffu, s, o);
        s2 += __shfl_xor_sync(0xffffffffu, s2, o);
    }
    if ((threadIdx.x & 31) == 0) { red0[threadIdx.x >> 5] = s; red1[threadIdx.x >> 5] = s2; }
    __syncthreads();
    float ts = 0.f, ts2 = 0.f;
    #pragma unroll
    for (int j = 0; j < 8; j++) { ts += red0[j]; ts2 += red1[j]; }
    const float inv_n = 1.f / (float)GN_ELEMS;
    float mean = ts * inv_n;
    float rstd = rsqrtf(ts2 * inv_n - mean * mean + 1e-3f);

    for (int idx = threadIdx.x; idx < GN_ELEMS / 4; idx += 256) {
        int n = idx >> 4, c4 = idx & 15;
        float4 v = base4[n * (CH / 4) + c4];
        int c = c4 * 4;
        float r0 = (v.x - mean) * rstd * gamma[grp * CPG + c]     + beta[grp * CPG + c];
        float r1 = (v.y - mean) * rstd * gamma[grp * CPG + c + 1] + beta[grp * CPG + c + 1];
        float r2 = (v.z - mean) * rstd * gamma[grp * CPG + c + 2] + beta[grp * CPG + c + 2];
        float r3 = (v.w - mean) * rstd * gamma[grp * CPG + c + 3] + beta[grp * CPG + c + 3];
        union { uint2 u; __nv_bfloat162 h2[2]; } pk;
        pk.h2[0] = __floats2bfloat162_rn(r0, r1);
        pk.h2[1] = __floats2bfloat162_rn(r2, r3);
        *(uint2*)&hout[n * CH + c] = pk.u;
    }
}

// ---------------------------------------------------------------------------
// Weight transpose (fp32 -> bf16, [N][K])
// ---------------------------------------------------------------------------
__global__ void transpose_w_kernel(const float* __restrict__ in,
                                   __nv_bfloat16* __restrict__ out,
                                   int R, int Ccol)
{
    __shared__ float tile[32][33];
    int c0 = blockIdx.x * 32, r0 = blockIdx.y * 32;
    int tx = threadIdx.x, ty = threadIdx.y;
    #pragma unroll
    for (int i = 0; i < 32; i += 8)
        tile[ty + i][tx] = in[(size_t)(r0 + ty + i) * Ccol + c0 + tx];
    __syncthreads();
    #pragma unroll
    for (int i = 0; i < 32; i += 8)
        out[(size_t)(c0 + ty + i) * R + r0 + tx] = __float2bfloat16_rn(tile[tx][ty + i]);
}

__global__ void transpose_v_kernel()
{
    __shared__ __nv_bfloat16 tile[32][33];
    int b = blockIdx.z;
    const __nv_bfloat16* in = g_qkv + (size_t)b * NPOS * QKVN + 2 * CH;
    __nv_bfloat16* out = g_vT + (size_t)b * CH * NPOS;
    int m0 = blockIdx.x * 32, c0 = blockIdx.y * 32;
    int tx = threadIdx.x, ty = threadIdx.y;
    #pragma unroll
    for (int i = 0; i < 32; i += 8)
        tile[ty + i][tx] = in[(size_t)(m0 + ty + i) * QKVN + c0 + tx];
    __syncthreads();
    #pragma unroll
    for (int i = 0; i < 32; i += 8)
        out[(size_t)(c0 + ty + i) * NPOS + m0 + tx] = tile[tx][ty + i];
}

// ---------------------------------------------------------------------------
// Softmax (vectorized): fp32 scores -> bf16 probs
// ---------------------------------------------------------------------------
__global__ __launch_bounds__(256) void softmax_kernel()
{
    const size_t row = blockIdx.x;
    const float4* s4 = (const float4*)(g_scores + row * NPOS);
    __nv_bfloat16* p = g_probs + row * NPOS;
    const int tid = threadIdx.x;
    __shared__ float red[8];

    float4 v = s4[tid];
    float mx = fmaxf(fmaxf(v.x, v.y), fmaxf(v.z, v.w));
    #pragma unroll
    for (int o = 16; o; o >>= 1) mx = fmaxf(mx, __shfl_xor_sync(0xffffffffu, mx, o));
    if ((tid & 31) == 0) red[tid >> 5] = mx;
    __syncthreads();
    mx = red[0];
    #pragma unroll
    for (int j = 1; j < 8; j++) mx = fmaxf(mx, red[j]);

    v.x = __expf(v.x - mx); v.y = __expf(v.y - mx);
    v.z = __expf(v.z - mx); v.w = __expf(v.w - mx);
    float sum = v.x + v.y + v.z + v.w;
    __syncthreads();
    #pragma unroll
    for (int o = 16; o; o >>= 1) sum += __shfl_xor_sync(0xffffffffu, sum, o);
    if ((tid & 31) == 0) red[tid >> 5] = sum;
    __syncthreads();
    float tot = 0.f;
    #pragma unroll
    for (int j = 0; j < 8; j++) tot += red[j];
    float rinv = 1.f / tot;
    union { uint2 u; __nv_bfloat162 h2[2]; } pk;
    pk.h2[0] = __floats2bfloat162_rn(v.x * rinv, v.y * rinv);
    pk.h2[1] = __floats2bfloat162_rn(v.z * rinv, v.w * rinv);
    *(uint2*)&p[tid * 4] = pk.u;
}

// ---------------------------------------------------------------------------
// NT bf16 GEMM, 4-stage cp.async pipeline + ldmatrix, 2 CTAs/SM.
// C[M][N] = A[M][K] * B[N][K]^T. BM=BN=128, BK=32, 8 warps (4x2).
// ---------------------------------------------------------------------------
template <int EPI>
__global__ __launch_bounds__(256, 2) void gemm_nt(
    const __nv_bfloat16* __restrict__ A, int lda, long long sA,
    const __nv_bfloat16* __restrict__ B, int ldb, long long sB,
    void* __restrict__ Cv, int ldc, long long sC,
    const float* __restrict__ bias, const float* __restrict__ resid,
    float scale, int K)
{
    extern __shared__ __nv_bfloat16 sm[];
    __nv_bfloat16* Asm = sm;
    __nv_bfloat16* Bsm = sm + STAGES * STG_ELEMS;

    const int z = blockIdx.z;
    A += (size_t)z * sA;
    B += (size_t)z * sB;

    const int tid = threadIdx.x;
    const int wid = tid >> 5, lane = tid & 31;
    const int wm = wid & 3, wn = wid >> 2;
    const int g = lane >> 2, t = lane & 3;
    const int m0 = blockIdx.y * BM;
    const int n0 = blockIdx.x * BN;

    const uint32_t sa_base = (uint32_t)__cvta_generic_to_shared(Asm);
    const uint32_t sb_base = (uint32_t)__cvta_generic_to_shared(Bsm);

    // cp.async thread mapping: 2 rows (r, r+64) x 1 16B chunk per matrix
    const int r_ld = tid >> 2;
    const int c_ld = (tid & 3) * 8;

    // ldmatrix lane mapping
    const int laneRow  = lane & 15;
    const int laneColH = (lane >> 4) * 8;
    const uint32_t aAddr0 = sa_base + (((wm * 32 + laneRow) * RS + laneColH) << 1);
    const uint32_t bAddr0 = sb_base + (((wn * 64 + laneRow) * RS + laneColH) << 1);

    float acc[2][8][4] = {};

    const int kit = K / BK;

#define LOAD_STAGE(s, ki) do {                                                     \
        int _k0 = (ki) * BK;                                                       \
        uint32_t _da = sa_base + (s) * (STG_ELEMS * 2);                            \
        uint32_t _db = sb_base + (s) * (STG_ELEMS * 2);                            \
        cp16(_da + (r_ld * RS + c_ld) * 2,        A + (size_t)(m0 + r_ld) * lda + _k0 + c_ld);        \
        cp16(_da + ((r_ld + 64) * RS + c_ld) * 2, A + (size_t)(m0 + r_ld + 64) * lda + _k0 + c_ld);   \
        cp16(_db + (r_ld * RS + c_ld) * 2,        B + (size_t)(n0 + r_ld) * ldb + _k0 + c_ld);        \
        cp16(_db + ((r_ld + 64) * RS + c_ld) * 2, B + (size_t)(n0 + r_ld + 64) * ldb + _k0 + c_ld);   \
        asm volatile("cp.async.commit_group;\n");                                  \
    } while (0)

    LOAD_STAGE(0, 0);
    LOAD_STAGE(1, 1);
    LOAD_STAGE(2, 2);

    for (int ki = 0; ki < kit; ki++) {
        asm volatile("cp.async.wait_group 2;\n");
        __syncthreads();
        const int st = ki & (STAGES - 1);
        const uint32_t aoff = aAddr0 + st * (STG_ELEMS * 2);
        const uint32_t boff = bAddr0 + st * (STG_ELEMS * 2);

        #pragma unroll
        for (int kk = 0; kk < BK; kk += 16) {
            uint32_t af[2][4], bf[8][2];
            ldm4(af[0][0], af[0][1], af[0][2], af[0][3], aoff + kk * 2);
            ldm4(af[1][0], af[1][1], af[1][2], af[1][3], aoff + (16 * RS + kk) * 2);
            #pragma unroll
            for (int p = 0; p < 4; p++) {
                uint32_t q0, q1, q2, q3;
                ldm4(q0, q1, q2, q3, boff + (p * 16 * RS + kk) * 2);
                bf[2 * p][0] = q0; bf[2 * p + 1][0] = q1;
                bf[2 * p][1] = q2; bf[2 * p + 1][1] = q3;
            }
            #pragma unroll
            for (int mi = 0; mi < 2; mi++)
                #pragma unroll
                for (int ni = 0; ni < 8; ni++) {
                    asm volatile(
                        "mma.sync.aligned.m16n8k16.row.col.f32.bf16.bf16.f32 "
                        "{%0,%1,%2,%3}, {%4,%5,%6,%7}, {%8,%9}, {%0,%1,%2,%3};\n"
                        : "+f"(acc[mi][ni][0]), "+f"(acc[mi][ni][1]),
                          "+f"(acc[mi][ni][2]), "+f"(acc[mi][ni][3])
                        : "r"(af[mi][0]), "r"(af[mi][1]), "r"(af[mi][2]), "r"(af[mi][3]),
                          "r"(bf[ni][0]), "r"(bf[ni][1]));
                }
        }

        if (ki + STAGES - 1 < kit) {
            LOAD_STAGE((ki + STAGES - 1) & (STAGES - 1), ki + STAGES - 1);
        } else {
            asm volatile("cp.async.commit_group;\n");
        }
    }
#undef LOAD_STAGE

    const size_t cbase = (size_t)z * sC;
    #pragma unroll
    for (int mi = 0; mi < 2; mi++) {
        #pragma unroll
        for (int ni = 0; ni < 8; ni++) {
            int row0 = m0 + wm * 32 + mi * 16 + g;
            int col  = n0 + wn * 64 + ni * 8 + t * 2;
            #pragma unroll
            for (int h2 = 0; h2 < 2; h2++) {
                int row = row0 + h2 * 8;
                float v0 = acc[mi][ni][h2 * 2 + 0];
                float v1 = acc[mi][ni][h2 * 2 + 1];
                size_t off = cbase + (size_t)row * ldc + col;
                if (EPI == 0) {
                    __nv_bfloat162 pk = __floats2bfloat162_rn(v0 + bias[col], v1 + bias[col + 1]);
                    *(__nv_bfloat162*)((__nv_bfloat16*)Cv + off) = pk;
                } else if (EPI == 1) {
                    *(float2*)((float*)Cv + off) = make_float2(v0 * scale, v1 * scale);
                } else if (EPI == 2) {
                    *(__nv_bfloat162*)((__nv_bfloat16*)Cv + off) = __floats2bfloat162_rn(v0, v1);
                } else {
                    float2 rx = *(const float2*)&resid[off];
                    *(float2*)((float*)Cv + off) =
                        make_float2(v0 + bias[col] + rx.x, v1 + bias[col + 1] + rx.y);
                }
            }
        }
    }
}

// ---------------------------------------------------------------------------
// Launch
// ---------------------------------------------------------------------------
extern "C" void kernel_launch(void* const* d_in, const int* in_sizes, int n_in,
                              void* d_out, int out_size)
{
    const float* x      = (const float*)d_in[0];
    const float* gamma  = (const float*)d_in[1];
    const float* beta   = (const float*)d_in[2];
    const float* w_qkv  = (const float*)d_in[3];
    const float* b_qkv  = (const float*)d_in[4];
    const float* w_proj = (const float*)d_in[5];
    const float* b_proj = (const float*)d_in[6];

    cudaFuncSetAttribute(gemm_nt<0>, cudaFuncAttributeMaxDynamicSharedMemorySize, SMEM_BYTES);
    cudaFuncSetAttribute(gemm_nt<1>, cudaFuncAttributeMaxDynamicSharedMemorySize, SMEM_BYTES);
    cudaFuncSetAttribute(gemm_nt<2>, cudaFuncAttributeMaxDynamicSharedMemorySize, SMEM_BYTES);
    cudaFuncSetAttribute(gemm_nt<3>, cudaFuncAttributeMaxDynamicSharedMemorySize, SMEM_BYTES);

    void *p_h, *p_wqkvT, *p_wprojT, *p_qkv, *p_vT, *p_scores, *p_probs, *p_attn;
    cudaGetSymbolAddress(&p_h, g_h);
    cudaGetSymbolAddress(&p_wqkvT, g_wqkvT);
    cudaGetSymbolAddress(&p_wprojT, g_wprojT);
    cudaGetSymbolAddress(&p_qkv, g_qkv);
    cudaGetSymbolAddress(&p_vT, g_vT);
    cudaGetSymbolAddress(&p_scores, g_scores);
    cudaGetSymbolAddress(&p_probs, g_probs);
    cudaGetSymbolAddress(&p_attn, g_attn);

    const __nv_bfloat16* hB      = (const __nv_bfloat16*)p_h;
    const __nv_bfloat16* wqkvTB  = (const __nv_bfloat16*)p_wqkvT;
    const __nv_bfloat16* wprojTB = (const __nv_bfloat16*)p_wprojT;
    const __nv_bfloat16* qkvB    = (const __nv_bfloat16*)p_qkv;
    const __nv_bfloat16* vTB     = (const __nv_bfloat16*)p_vT;
    const __nv_bfloat16* probsB  = (const __nv_bfloat16*)p_probs;
    const __nv_bfloat16* attnB   = (const __nv_bfloat16*)p_attn;

    transpose_w_kernel<<<dim3(QKVN / 32, CH / 32), dim3(32, 8)>>>(w_qkv, (__nv_bfloat16*)p_wqkvT, CH, QKVN);
    transpose_w_kernel<<<dim3(CH / 32, CH / 32), dim3(32, 8)>>>(w_proj, (__nv_bfloat16*)p_wprojT, CH, CH);
    groupnorm_kernel<<<BATCH * GROUPS, 256>>>(x, gamma, beta);

    gemm_nt<0><<<dim3(QKVN / BN, MTOT / BM, 1), 256, SMEM_BYTES>>>(
        hB, CH, 0, wqkvTB, CH, 0, p_qkv, QKVN, 0, b_qkv, nullptr, 0.f, CH);

    transpose_v_kernel<<<dim3(NPOS / 32, CH / 32, BATCH), dim3(32, 8)>>>();

    const float scale = 0.044194173824159216f; // 1/sqrt(512)
    gemm_nt<1><<<dim3(NPOS / BN, NPOS / BM, BATCH), 256, SMEM_BYTES>>>(
        qkvB, QKVN, (long long)NPOS * QKVN,
        qkvB + CH, QKVN, (long long)NPOS * QKVN,
        p_scores, NPOS, (long long)NPOS * NPOS,
        nullptr, nullptr, scale, CH);

    softmax_kernel<<<MTOT, 256>>>();

    gemm_nt<2><<<dim3(CH / BN, NPOS / BM, BATCH), 256, SMEM_BYTES>>>(
        probsB, NPOS, (long long)NPOS * NPOS,
        vTB, NPOS, (long long)CH * NPOS,
        p_attn, CH, (long long)NPOS * CH,
        nullptr, nullptr, 0.f, NPOS);

    gemm_nt<3><<<dim3(CH / BN, MTOT / BM, 1), 256, SMEM_BYTES>>>(
        attnB, CH, 0, wprojTB, CH, 0, d_out, CH, 0, b_proj, x, 0.f, CH);
}